// round 6
// baseline (speedup 1.0000x reference)
#include <cuda_runtime.h>

#define B    100
#define DIN  2048
#define DH   1024
#define DOUT 1000

__device__ float d_hacc[B * DH];   // gemm1 + b1-sum accumulator (pre-scaled 1/DIN)
__device__ int   d_cnt[16];        // last-reader counters for d_hacc k-slices
__device__ int   d_tick1;          // mega1 ticket counter (reset by mega2)
__device__ int   d_tick2;          // mega2 ticket counter (reset by mega1)

#define GRID      888             // 148 SMs x 6 blocks
#define G1_BLOCKS 256             // gemm1: 16 ntiles x 16 ksplits (kc=128)
#define G2_BLOCKS 256             // gemm2: 16 ntiles x 16 ksplits (kc=64)
#define OZ_UNITS  98              // out-zero units: 98*256 float4 >= 25000
#define R1_UNITS  3200            // b1: 100 batches x 32 chunks of 64 rows
#define T1_TOTAL  (OZ_UNITS + R1_UNITS)
#define R2_UNITS  3200            // b2: 100 batches x 32 chunks of 32 rows
#define T2_TOTAL  R2_UNITS

// ---------------------------------------------------------------------------
// SIMT GEMM tile: all 100 M-rows x 64 N-cols, K range [k0, k0+kc).
// 256 threads: thread owns 7 m x 4 n. Accumulates scale*r into acc atomically.
// relu_in: max(v,0) applied to A on load.
// zslice >= 0: last-reader re-zero of d_hacc cols [zslice*64, +64) — the 16th
// reading block restores the d_hacc==0 invariant for the next graph replay.
__device__ __forceinline__ void gemm_block(const float* __restrict__ A,
                                           const float* __restrict__ Wm,
                                           float* __restrict__ acc,
                                           int K, int N, int ldacc,
                                           int k0, int kc, int n0,
                                           float scale, bool relu_in,
                                           int zslice) {
    __shared__ __align__(16) float xs[112][33]; // pad 33: strips hit distinct banks
    __shared__ __align__(16) float ws[32][64];
    __shared__ int do_zero;

    const int tid = threadIdx.x;
    const int nl4 = tid & 15;        // 16 lanes * 4 cols = 64
    const int m0  = (tid >> 4) * 7;  // 16 strips * 7 = 112 >= 100

    float r[7][4];
#pragma unroll
    for (int i = 0; i < 7; ++i)
#pragma unroll
        for (int j = 0; j < 4; ++j) r[i][j] = 0.f;

    for (int kb = k0; kb < k0 + kc; kb += 32) {
        for (int idx = tid; idx < 112 * 32; idx += 256) {
            int m = idx >> 5, kk = idx & 31;
            float v = (m < B) ? A[(long long)m * K + kb + kk] : 0.f;
            if (relu_in) v = fmaxf(v, 0.f);
            xs[m][kk] = v;
        }
        for (int idx = tid; idx < 32 * 64; idx += 256) {
            int kk = idx >> 6, nn = idx & 63;
            int nc = n0 + nn;
            ws[kk][nn] = (nc < N) ? Wm[(long long)(kb + kk) * N + nc] : 0.f;
        }
        __syncthreads();
#pragma unroll
        for (int kk = 0; kk < 32; ++kk) {
            float4 wv = *(const float4*)&ws[kk][nl4 * 4];
#pragma unroll
            for (int mi = 0; mi < 7; ++mi) {
                float xv = xs[m0 + mi][kk];
                r[mi][0] += xv * wv.x; r[mi][1] += xv * wv.y;
                r[mi][2] += xv * wv.z; r[mi][3] += xv * wv.w;
            }
        }
        __syncthreads();
    }

#pragma unroll
    for (int mi = 0; mi < 7; ++mi) {
        int m = m0 + mi;
        if (m < B) {
            int n = n0 + nl4 * 4;
#pragma unroll
            for (int j = 0; j < 4; ++j)
                if (n + j < N)
                    atomicAdd(&acc[(long long)m * ldacc + n + j], r[mi][j] * scale);
        }
    }

    if (zslice >= 0) {
        if (tid == 0) {
            int old = atomicAdd(&d_cnt[zslice], 1);
            do_zero = (old == 15);
            if (old == 15) d_cnt[zslice] = 0;   // self-reset for next replay
        }
        __syncthreads();
        if (do_zero) {
            int c0 = zslice * 64;
            for (int idx = tid; idx < B * 64; idx += 256)
                d_hacc[(idx >> 6) * DH + c0 + (idx & 63)] = 0.f;
        }
        __syncthreads();
    }
}

// ---------------------------------------------------------------------------
// Column-sum of `rows` rows of a [rows_total x width] slab into acc row b,
// scaled. Coalesced float4 loads. No syncs inside (safe under inactive lanes).
__device__ __forceinline__ void reduce_block(const float* __restrict__ src,
                                             float* __restrict__ acc,
                                             int b, int chunk, int rows,
                                             int rows_total, int width,
                                             float scale) {
    const int wq = width >> 2;
    const int j4 = threadIdx.x;
    if (j4 >= wq) return;
    const long long base = (long long)b * rows_total * width +
                           (long long)chunk * rows * width + j4 * 4;
    const float4* p = (const float4*)(src + base);
    float4 s = make_float4(0.f, 0.f, 0.f, 0.f);
#pragma unroll 16
    for (int i = 0; i < rows; ++i) {
        float4 v = p[(long long)i * wq];
        s.x += v.x; s.y += v.y; s.z += v.z; s.w += v.w;
    }
    float* o = acc + (long long)b * width + j4 * 4;
    atomicAdd(o + 0, s.x * scale); atomicAdd(o + 1, s.y * scale);
    atomicAdd(o + 2, s.z * scale); atomicAdd(o + 3, s.w * scale);
}

// ---------------------------------------------------------------------------
// mega1: 888 persistent blocks. bids [0,256): gemm1 tile first. Then all
// blocks drain the ticket pool: 98 out-zero units + 3200 b1-reduce units.
__global__ void __launch_bounds__(256, 6)
mega1_kernel(const float* __restrict__ x,
             const float* __restrict__ W1,
             const float* __restrict__ b1,
             float* __restrict__ out) {
    __shared__ int s_t;
    const int bid = blockIdx.x;
    const int tid = threadIdx.x;

    // Reset mega2's ticket counter for this replay (mega2 of the previous
    // replay has fully completed — stream is serial).
    if (bid == 0 && tid == 0) d_tick2 = 0;

    if (bid < G1_BLOCKS) {
        int nt = bid & 15, ks = bid >> 4;
        gemm_block(x, W1, d_hacc, DIN, DH, DH, ks * 128, 128, nt * 64,
                   1.0f / DIN, false, -1);
    }

    for (;;) {
        __syncthreads();
        if (tid == 0) s_t = atomicAdd(&d_tick1, 1);
        __syncthreads();
        int t = s_t;
        if (t >= T1_TOTAL) break;
        if (t < OZ_UNITS) {
            int i4 = t * 256 + tid;
            if (i4 < (B * DOUT) / 4)
                ((float4*)out)[i4] = make_float4(0.f, 0.f, 0.f, 0.f);
        } else {
            int u = t - OZ_UNITS;
            reduce_block(b1, d_hacc, u >> 5, u & 31, 64, DIN, DH, 1.0f / DIN);
        }
    }
}

// mega2: 888 persistent blocks. bids [0,256): gemm2 tile (relu on A-load,
// last-reader re-zero of d_hacc, accumulate into out). Then all blocks drain
// the b2-reduce pool (3200 units of 32 rows).
__global__ void __launch_bounds__(256, 6)
mega2_kernel(const float* __restrict__ W2,
             const float* __restrict__ b2,
             float* __restrict__ out) {
    __shared__ int s_t;
    const int bid = blockIdx.x;
    const int tid = threadIdx.x;

    // Reset mega1's ticket counter for the next replay (mega1 of this replay
    // has fully completed).
    if (bid == 0 && tid == 0) d_tick1 = 0;

    if (bid < G2_BLOCKS) {
        int nt = bid & 15, ks = bid >> 4;
        gemm_block(d_hacc, W2, out, DH, DOUT, DOUT, ks * 64, 64, nt * 64,
                   1.0f / DH, true, ks);
    }

    for (;;) {
        __syncthreads();
        if (tid == 0) s_t = atomicAdd(&d_tick2, 1);
        __syncthreads();
        int t = s_t;
        if (t >= T2_TOTAL) break;
        reduce_block(b2, out, t >> 5, t & 31, 32, DH, DOUT, 1.0f / DH);
    }
}

// ---------------------------------------------------------------------------
extern "C" void kernel_launch(void* const* d_in, const int* in_sizes, int n_in,
                              void* d_out, int out_size) {
    const float* x  = (const float*)d_in[0];
    const float* W1 = (const float*)d_in[1];
    const float* b1 = (const float*)d_in[2];
    const float* W2 = (const float*)d_in[3];
    const float* b2 = (const float*)d_in[4];
    float* out = (float*)d_out;

    mega1_kernel<<<GRID, 256>>>(x, W1, b1, out);
    mega2_kernel<<<GRID, 256>>>(W2, b2, out);
}

// round 7
// speedup vs baseline: 1.0875x; 1.0875x over previous
#include <cuda_runtime.h>

#define B    100
#define DIN  2048
#define DH   1024
#define DOUT 1000

__device__ __align__(16) float d_hacc[B * DH];   // gemm1 + b1 acc (pre-scaled 1/DIN)
__device__ __align__(16) float d_oacc[B * DOUT]; // mega1's b2 partial (pre-scaled 1/DH)
__device__ int d_cnt[16];                        // last-reader counters (d_hacc slices)

#define R2_SPLIT  60               // b2 batches [0,60) in mega1, [60,100) in mega2
#define G1_BLOCKS 256              // gemm1: 16 ntiles x 16 ksplits (kc=128)
#define OZ_BLOCKS 98               // out-zero: 98*256 float4 = 25088 >= 25000
#define R1_BLOCKS 1600             // b1: 100 batches x 16 chunks (128 rows)
#define R2A_BLOCKS (R2_SPLIT * 8)  // 480: b2 128-row chunks -> d_oacc
#define G2_BLOCKS 256              // gemm2: 16 ntiles x 16 ksplits (kc=64)
#define R2B_BLOCKS ((B - R2_SPLIT) * 8) // 320: b2 128-row chunks -> out
#define MG_BLOCKS 98               // merge d_oacc -> out, re-zero d_oacc

// ---------------------------------------------------------------------------
// SIMT GEMM tile: all 100 M-rows x 64 N-cols, K range [k0, k0+kc).
// 256 threads: thread owns 7 m x 4 n. Accumulates scale*r into acc atomically.
// relu_in: max(v,0) on A load. zslice >= 0: last-reader re-zero of d_hacc
// cols [zslice*64, +64) restoring the zero invariant for the next replay.
__device__ __forceinline__ void gemm_block(const float* __restrict__ A,
                                           const float* __restrict__ Wm,
                                           float* __restrict__ acc,
                                           int K, int N, int ldacc,
                                           int k0, int kc, int n0,
                                           float scale, bool relu_in,
                                           int zslice) {
    __shared__ __align__(16) float xs[112][33]; // pad 33: strips hit distinct banks
    __shared__ __align__(16) float ws[32][64];
    __shared__ int do_zero;

    const int tid = threadIdx.x;
    const int nl4 = tid & 15;        // 16 lanes * 4 cols = 64
    const int m0  = (tid >> 4) * 7;  // 16 strips * 7 = 112 >= 100

    float r[7][4];
#pragma unroll
    for (int i = 0; i < 7; ++i)
#pragma unroll
        for (int j = 0; j < 4; ++j) r[i][j] = 0.f;

    for (int kb = k0; kb < k0 + kc; kb += 32) {
        for (int idx = tid; idx < 112 * 32; idx += 256) {
            int m = idx >> 5, kk = idx & 31;
            float v = (m < B) ? A[(long long)m * K + kb + kk] : 0.f;
            if (relu_in) v = fmaxf(v, 0.f);
            xs[m][kk] = v;
        }
        for (int idx = tid; idx < 32 * 64; idx += 256) {
            int kk = idx >> 6, nn = idx & 63;
            int nc = n0 + nn;
            ws[kk][nn] = (nc < N) ? Wm[(long long)(kb + kk) * N + nc] : 0.f;
        }
        __syncthreads();
#pragma unroll
        for (int kk = 0; kk < 32; ++kk) {
            float4 wv = *(const float4*)&ws[kk][nl4 * 4];
#pragma unroll
            for (int mi = 0; mi < 7; ++mi) {
                float xv = xs[m0 + mi][kk];
                r[mi][0] += xv * wv.x; r[mi][1] += xv * wv.y;
                r[mi][2] += xv * wv.z; r[mi][3] += xv * wv.w;
            }
        }
        __syncthreads();
    }

#pragma unroll
    for (int mi = 0; mi < 7; ++mi) {
        int m = m0 + mi;
        if (m < B) {
            int n = n0 + nl4 * 4;
#pragma unroll
            for (int j = 0; j < 4; ++j)
                if (n + j < N)
                    atomicAdd(&acc[(long long)m * ldacc + n + j], r[mi][j] * scale);
        }
    }

    if (zslice >= 0) {
        if (tid == 0) {
            int old = atomicAdd(&d_cnt[zslice], 1);
            do_zero = (old == 15);
            if (old == 15) d_cnt[zslice] = 0;   // self-reset for next replay
        }
        __syncthreads();
        if (do_zero) {
            int c0 = zslice * 64;
            for (int idx = tid; idx < B * 64; idx += 256)
                d_hacc[(idx >> 6) * DH + c0 + (idx & 63)] = 0.f;
        }
    }
}

// ---------------------------------------------------------------------------
// Column-sum of `rows` rows of a [rows_total x width] slab into acc row b,
// scaled. Coalesced float4 loads; long 128-row bursts for deep MLP.
__device__ __forceinline__ void reduce_block(const float* __restrict__ src,
                                             float* __restrict__ acc,
                                             int b, int chunk, int rows,
                                             int rows_total, int width,
                                             float scale) {
    const int wq = width >> 2;
    const int j4 = threadIdx.x;
    if (j4 >= wq) return;
    const long long base = (long long)b * rows_total * width +
                           (long long)chunk * rows * width + j4 * 4;
    const float4* p = (const float4*)(src + base);
    float4 s = make_float4(0.f, 0.f, 0.f, 0.f);
#pragma unroll 16
    for (int i = 0; i < rows; ++i) {
        float4 v = p[(long long)i * wq];
        s.x += v.x; s.y += v.y; s.z += v.z; s.w += v.w;
    }
    float* o = acc + (long long)b * width + j4 * 4;
    atomicAdd(o + 0, s.x * scale); atomicAdd(o + 1, s.y * scale);
    atomicAdd(o + 2, s.z * scale); atomicAdd(o + 3, s.w * scale);
}

// ---------------------------------------------------------------------------
// mega1: gemm1 (256) + out-zero (98) + b1-reduce (1600) + b2[0,60) (480).
// No launch_bounds: 56 regs -> deep front-batched load MLP (R2 evidence).
__global__ void mega1_kernel(const float* __restrict__ x,
                             const float* __restrict__ W1,
                             const float* __restrict__ b1,
                             const float* __restrict__ b2,
                             float* __restrict__ out) {
    int bid = blockIdx.x;
    if (bid < G1_BLOCKS) {
        int nt = bid & 15, ks = bid >> 4;
        gemm_block(x, W1, d_hacc, DIN, DH, DH, ks * 128, 128, nt * 64,
                   1.0f / DIN, false, -1);
    } else if (bid < G1_BLOCKS + OZ_BLOCKS) {
        int i4 = (bid - G1_BLOCKS) * 256 + threadIdx.x;
        if (i4 < (B * DOUT) / 4)
            ((float4*)out)[i4] = make_float4(0.f, 0.f, 0.f, 0.f);
    } else if (bid < G1_BLOCKS + OZ_BLOCKS + R1_BLOCKS) {
        int r = bid - (G1_BLOCKS + OZ_BLOCKS);
        reduce_block(b1, d_hacc, r >> 4, r & 15, 128, DIN, DH, 1.0f / DIN);
    } else {
        int r = bid - (G1_BLOCKS + OZ_BLOCKS + R1_BLOCKS);
        reduce_block(b2, d_oacc, r >> 3, r & 7, 128, DH, DOUT, 1.0f / DH);
    }
}

// mega2: gemm2 (256, relu on A-load, d_hacc re-zero) + b2[60,100) (320)
//        + merge d_oacc into out & re-zero d_oacc (98).
__global__ void mega2_kernel(const float* __restrict__ W2,
                             const float* __restrict__ b2,
                             float* __restrict__ out) {
    int bid = blockIdx.x;
    if (bid < G2_BLOCKS) {
        int nt = bid & 15, ks = bid >> 4;
        gemm_block(d_hacc, W2, out, DH, DOUT, DOUT, ks * 64, 64, nt * 64,
                   1.0f / DH, true, ks);
    } else if (bid < G2_BLOCKS + R2B_BLOCKS) {
        int r = bid - G2_BLOCKS;
        reduce_block(b2, out, R2_SPLIT + (r >> 3), r & 7, 128, DH, DOUT,
                     1.0f / DH);
    } else {
        int i4 = (bid - (G2_BLOCKS + R2B_BLOCKS)) * 256 + threadIdx.x;
        if (i4 < (B * DOUT) / 4) {
            float4 v = ((const float4*)d_oacc)[i4];
            float* o = out + i4 * 4;
            atomicAdd(o + 0, v.x); atomicAdd(o + 1, v.y);
            atomicAdd(o + 2, v.z); atomicAdd(o + 3, v.w);
            ((float4*)d_oacc)[i4] = make_float4(0.f, 0.f, 0.f, 0.f);
        }
    }
}

// ---------------------------------------------------------------------------
extern "C" void kernel_launch(void* const* d_in, const int* in_sizes, int n_in,
                              void* d_out, int out_size) {
    const float* x  = (const float*)d_in[0];
    const float* W1 = (const float*)d_in[1];
    const float* b1 = (const float*)d_in[2];
    const float* W2 = (const float*)d_in[3];
    const float* b2 = (const float*)d_in[4];
    float* out = (float*)d_out;

    mega1_kernel<<<G1_BLOCKS + OZ_BLOCKS + R1_BLOCKS + R2A_BLOCKS, 256>>>(
        x, W1, b1, b2, out);
    mega2_kernel<<<G2_BLOCKS + R2B_BLOCKS + MG_BLOCKS, 256>>>(W2, b2, out);
}